// round 1
// baseline (speedup 1.0000x reference)
#include <cuda_runtime.h>

// Problem constants
#define BB 4
#define SS 2048
#define DD 1024
#define HH 16
#define DH 64
#define MTOT (BB*SS)          // 8192 rows
#define LOG2E 1.4426950408889634f

// Scratch (allocation-free rule: __device__ globals)
__device__ float g_q[(size_t)MTOT * DD];
__device__ float g_k[(size_t)MTOT * DD];
__device__ float g_v[(size_t)MTOT * DD];
__device__ float g_o[(size_t)MTOT * DD];

// ---------------------------------------------------------------------------
// Tiled GEMM + bias: C[M=8192, N=1024] = A[8192,1024] * W + bias
// HEADED=true: W is [H, D, 64]  (per-head weights; block col == head)
// HEADED=false: W is [1024, 1024] row-major
// Tile: 64x64, BK=16, 256 threads, 4x4 micro-tile per thread.
// ---------------------------------------------------------------------------
template<bool HEADED>
__global__ __launch_bounds__(256)
void gemm_bias(const float* __restrict__ A, const float* __restrict__ W,
               const float* __restrict__ bias, float* __restrict__ C)
{
    const int K = 1024, N = 1024;
    __shared__ float As[16][64];
    __shared__ float Bs[16][64];
    int tid = threadIdx.x;
    int bn = blockIdx.x;     // 0..15
    int bm = blockIdx.y;     // 0..127
    int tx = tid & 15, ty = tid >> 4;

    const float* Wp;
    int ldw;
    if (HEADED) { Wp = W + (size_t)bn * K * 64; ldw = 64; }   // head bn, [K,64]
    else        { Wp = W + bn * 64;            ldw = N;  }

    float acc[4][4];
    #pragma unroll
    for (int i = 0; i < 4; i++)
        #pragma unroll
        for (int j = 0; j < 4; j++) acc[i][j] = 0.f;

    int ar  = tid >> 2;      // A tile row 0..63
    int ac4 = tid & 3;       // A float4 col 0..3 (covers k 0..15)
    int wr  = tid >> 4;      // W tile row (k) 0..15
    int wc4 = tid & 15;      // W float4 col 0..15

    const float* Ap = A + (size_t)(bm * 64 + ar) * K + ac4 * 4;

    for (int kt = 0; kt < K; kt += 16) {
        float4 av = *(const float4*)(Ap + kt);
        float4 wv = *(const float4*)(Wp + (size_t)(kt + wr) * ldw + wc4 * 4);
        As[ac4 * 4 + 0][ar] = av.x;
        As[ac4 * 4 + 1][ar] = av.y;
        As[ac4 * 4 + 2][ar] = av.z;
        As[ac4 * 4 + 3][ar] = av.w;
        *(float4*)&Bs[wr][wc4 * 4] = wv;
        __syncthreads();
        #pragma unroll
        for (int kk = 0; kk < 16; kk++) {
            float4 a = *(const float4*)&As[kk][ty * 4];
            float4 b = *(const float4*)&Bs[kk][tx * 4];
            float ax[4] = {a.x, a.y, a.z, a.w};
            float bx[4] = {b.x, b.y, b.z, b.w};
            #pragma unroll
            for (int i = 0; i < 4; i++)
                #pragma unroll
                for (int j = 0; j < 4; j++) acc[i][j] += ax[i] * bx[j];
        }
        __syncthreads();
    }

    #pragma unroll
    for (int i = 0; i < 4; i++) {
        int m = bm * 64 + ty * 4 + i;
        int n = bn * 64 + tx * 4;
        float4 outv;
        outv.x = acc[i][0] + bias[n + 0];
        outv.y = acc[i][1] + bias[n + 1];
        outv.z = acc[i][2] + bias[n + 2];
        outv.w = acc[i][3] + bias[n + 3];
        *(float4*)(C + (size_t)m * N + n) = outv;
    }
}

// ---------------------------------------------------------------------------
// Flash-attention (fp32): one thread per query row, 128 rows per block.
// K/V tiles of 64 rows in SMEM; scores processed in chunks of 16 (online
// softmax) to bound register pressure.
// q/k/v layout: [b, s, h, e] (row stride H*DH = 1024)
// ---------------------------------------------------------------------------
__global__ __launch_bounds__(128)
void attn_kernel(const float* __restrict__ q, const float* __restrict__ k,
                 const float* __restrict__ v, float* __restrict__ o)
{
    __shared__ float Ks[64][64];
    __shared__ float Vs[64][64];
    int b = blockIdx.z, h = blockIdx.y;
    int tid = threadIdx.x;
    int row = blockIdx.x * 128 + tid;
    const int rowstride = HH * DH;   // 1024

    const float* qp = q + ((size_t)(b * SS + row) * HH + h) * DH;
    float qreg[64];
    #pragma unroll
    for (int e4 = 0; e4 < 16; e4++) {
        float4 t = ((const float4*)qp)[e4];
        qreg[e4 * 4 + 0] = t.x; qreg[e4 * 4 + 1] = t.y;
        qreg[e4 * 4 + 2] = t.z; qreg[e4 * 4 + 3] = t.w;
    }
    float acc[64];
    #pragma unroll
    for (int e = 0; e < 64; e++) acc[e] = 0.f;
    float mrun = -1e30f, lrun = 0.f;

    const float* kb0 = k + ((size_t)b * SS * HH + h) * DH;
    const float* vb0 = v + ((size_t)b * SS * HH + h) * DH;

    for (int t0 = 0; t0 < SS; t0 += 64) {
        __syncthreads();
        #pragma unroll
        for (int i = 0; i < 8; i++) {
            int idx = tid + i * 128;          // 0..1023 float4 slots
            int r = idx >> 4, c4 = idx & 15;
            ((float4*)&Ks[r][0])[c4] =
                ((const float4*)(kb0 + (size_t)(t0 + r) * rowstride))[c4];
            ((float4*)&Vs[r][0])[c4] =
                ((const float4*)(vb0 + (size_t)(t0 + r) * rowstride))[c4];
        }
        __syncthreads();

        #pragma unroll 1
        for (int jc = 0; jc < 4; jc++) {     // 4 chunks of 16 keys
            float s[16];
            #pragma unroll
            for (int j = 0; j < 16; j++) {
                float d = 0.f;
                #pragma unroll
                for (int e4 = 0; e4 < 16; e4++) {
                    float4 kv = ((const float4*)&Ks[jc * 16 + j][0])[e4];
                    d += qreg[e4 * 4 + 0] * kv.x;
                    d += qreg[e4 * 4 + 1] * kv.y;
                    d += qreg[e4 * 4 + 2] * kv.z;
                    d += qreg[e4 * 4 + 3] * kv.w;
                }
                s[j] = d * 0.125f;           // 1/sqrt(64)
            }
            float mt = mrun;
            #pragma unroll
            for (int j = 0; j < 16; j++) mt = fmaxf(mt, s[j]);
            float corr = __expf(mrun - mt);
            mrun = mt;
            float psum = 0.f;
            #pragma unroll
            for (int j = 0; j < 16; j++) { s[j] = __expf(s[j] - mt); psum += s[j]; }
            lrun = lrun * corr + psum;
            #pragma unroll
            for (int e = 0; e < 64; e++) acc[e] *= corr;
            #pragma unroll
            for (int j = 0; j < 16; j++) {
                float pj = s[j];
                #pragma unroll
                for (int e4 = 0; e4 < 16; e4++) {
                    float4 vv = ((const float4*)&Vs[jc * 16 + j][0])[e4];
                    acc[e4 * 4 + 0] += pj * vv.x;
                    acc[e4 * 4 + 1] += pj * vv.y;
                    acc[e4 * 4 + 2] += pj * vv.z;
                    acc[e4 * 4 + 3] += pj * vv.w;
                }
            }
        }
    }

    float inv = 1.f / lrun;
    float* op = o + ((size_t)(b * SS + row) * HH + h) * DH;
    #pragma unroll
    for (int e4 = 0; e4 < 16; e4++) {
        float4 t;
        t.x = acc[e4 * 4 + 0] * inv; t.y = acc[e4 * 4 + 1] * inv;
        t.z = acc[e4 * 4 + 2] * inv; t.w = acc[e4 * 4 + 3] * inv;
        ((float4*)op)[e4] = t;
    }
}

// ---------------------------------------------------------------------------
// Launch
// inputs: queries, keys, values, Wq, bq, Wk, bk, Wv, bv, Wo, bo
// ---------------------------------------------------------------------------
extern "C" void kernel_launch(void* const* d_in, const int* in_sizes, int n_in,
                              void* d_out, int out_size)
{
    (void)in_sizes; (void)n_in; (void)out_size;
    const float* queries = (const float*)d_in[0];
    const float* keys    = (const float*)d_in[1];
    const float* values  = (const float*)d_in[2];
    const float* Wq = (const float*)d_in[3];
    const float* bq = (const float*)d_in[4];
    const float* Wk = (const float*)d_in[5];
    const float* bk = (const float*)d_in[6];
    const float* Wv = (const float*)d_in[7];
    const float* bv = (const float*)d_in[8];
    const float* Wo = (const float*)d_in[9];
    const float* bo = (const float*)d_in[10];
    float* out = (float*)d_out;

    float *pq, *pk, *pv, *po;
    cudaGetSymbolAddress((void**)&pq, g_q);
    cudaGetSymbolAddress((void**)&pk, g_k);
    cudaGetSymbolAddress((void**)&pv, g_v);
    cudaGetSymbolAddress((void**)&po, g_o);

    dim3 ggrid(16, 128);            // N/64 x M/64
    gemm_bias<true><<<ggrid, 256>>>(queries, Wq, bq, pq);
    gemm_bias<true><<<ggrid, 256>>>(keys,    Wk, bk, pk);
    gemm_bias<true><<<ggrid, 256>>>(values,  Wv, bv, pv);

    dim3 agrid(SS / 128, HH, BB);   // (16, 16, 4)
    attn_kernel<<<agrid, 128>>>(pq, pk, pv, po);

    gemm_bias<false><<<ggrid, 256>>>(po, Wo, bo, out);
}